// round 13
// baseline (speedup 1.0000x reference)
#include <cuda_runtime.h>
#include <cuda_bf16.h>
#include <cstdint>

#define BB 32
#define IN_C 512
#define HW 4096
#define CODE 256
#define NCLASSES 4
#define MEMN 20
#define DECAYF 0.9f
#define EPSF 1e-12f
#define NTP 128

typedef long long ll;

// Deterministic scratch (no atomics anywhere).
__device__ float g_partial[BB * CODE * NTP];
__device__ float g_feat[BB * CODE];
__device__ float g_queue[NCLASSES * MEMN * CODE];

// Pre-converted bf16 hi/lo of Wp.
__device__ __nv_bfloat16 g_wp_hi[CODE * IN_C];
__device__ __nv_bfloat16 g_wp_lo[CODE * IN_C];

// ---------------------------------------------------------------------------
// helpers
// ---------------------------------------------------------------------------
__device__ __forceinline__ uint32_t smem_u32(const void* p) {
    uint32_t a;
    asm("{ .reg .u64 t; cvta.to.shared.u64 t, %1; cvt.u32.u64 %0, t; }" : "=r"(a) : "l"(p));
    return a;
}
__device__ __forceinline__ void ldsm_x4(uint32_t a[4], uint32_t addr) {
    asm volatile("ldmatrix.sync.aligned.m8n8.x4.shared.b16 {%0,%1,%2,%3}, [%4];"
                 : "=r"(a[0]), "=r"(a[1]), "=r"(a[2]), "=r"(a[3]) : "r"(addr));
}
__device__ __forceinline__ void ldsm_x2t(uint32_t b[2], uint32_t addr) {
    asm volatile("ldmatrix.sync.aligned.m8n8.x2.trans.shared.b16 {%0,%1}, [%2];"
                 : "=r"(b[0]), "=r"(b[1]) : "r"(addr));
}
__device__ __forceinline__ void mma_bf16(float d[4], const uint32_t a[4], const uint32_t b[2]) {
    asm volatile("mma.sync.aligned.m16n8k16.row.col.f32.bf16.bf16.f32 "
                 "{%0,%1,%2,%3}, {%4,%5,%6,%7}, {%8,%9}, {%0,%1,%2,%3};"
                 : "+f"(d[0]), "+f"(d[1]), "+f"(d[2]), "+f"(d[3])
                 : "r"(a[0]), "r"(a[1]), "r"(a[2]), "r"(a[3]), "r"(b[0]), "r"(b[1]));
}
__device__ __forceinline__ void cpasync16(uint32_t dst, const void* src) {
    asm volatile("cp.async.cg.shared.global [%0], [%1], 16;" :: "r"(dst), "l"(src));
}
#define CP_COMMIT() asm volatile("cp.async.commit_group;" ::: "memory")
#define CP_WAIT0()  asm volatile("cp.async.wait_group 0;" ::: "memory")

__device__ __forceinline__ void split4(float4 v, uint2& hi, uint2& lo) {
    __nv_bfloat16 h0 = __float2bfloat16_rn(v.x), h1 = __float2bfloat16_rn(v.y);
    __nv_bfloat16 h2 = __float2bfloat16_rn(v.z), h3 = __float2bfloat16_rn(v.w);
    float r0 = v.x - __bfloat162float(h0), r1 = v.y - __bfloat162float(h1);
    float r2 = v.z - __bfloat162float(h2), r3 = v.w - __bfloat162float(h3);
    __nv_bfloat16 l0 = __float2bfloat16_rn(r0), l1 = __float2bfloat16_rn(r1);
    __nv_bfloat16 l2 = __float2bfloat16_rn(r2), l3 = __float2bfloat16_rn(r3);
    hi.x = (uint32_t)__bfloat16_as_ushort(h0) | ((uint32_t)__bfloat16_as_ushort(h1) << 16);
    hi.y = (uint32_t)__bfloat16_as_ushort(h2) | ((uint32_t)__bfloat16_as_ushort(h3) << 16);
    lo.x = (uint32_t)__bfloat16_as_ushort(l0) | ((uint32_t)__bfloat16_as_ushort(l1) << 16);
    lo.y = (uint32_t)__bfloat16_as_ushort(l2) | ((uint32_t)__bfloat16_as_ushort(l3) << 16);
}

__device__ __forceinline__ int get_label(const int* lab, int i) {
    bool odd_zero = true;
#pragma unroll
    for (int k = 1; k < 32; k += 2) odd_zero &= (lab[k] == 0);
    return odd_zero ? lab[2 * i] : lab[i];
}

// ===========================================================================
// Kernel 0: Wp fp32 -> bf16 hi/lo.
// ===========================================================================
__global__ __launch_bounds__(256) void convert_wp(const float* __restrict__ Wp) {
    const int i = (blockIdx.x * 256 + threadIdx.x) * 4;
    float4 v = *(const float4*)(Wp + i);
    uint2 hi, lo; split4(v, hi, lo);
    *(uint2*)(g_wp_hi + i) = hi;
    *(uint2*)(g_wp_lo + i) = lo;
}

// ===========================================================================
// Kernel 1: HMMA bf16-split GEMM, fused B conversion, M=256 CTA tile.
// (unchanged, protected — measured ~230 us)
// ===========================================================================
#define KC 32
#define NCHUNK 16
#define A_STR 80
#define B_STR 272
#define A_HI 0
#define A_LO 20480
#define B_HI 40960
#define B_LO 49664
#define BUF 58368
#define PREDS (2 * BUF)
#define SMEM_GEMM (PREDS + 512 + 16)

__global__ __launch_bounds__(512, 1) void gemm_proj_mma(
    const float* __restrict__ feats, const float* __restrict__ preds,
    const float* __restrict__ bias_p, float* __restrict__ out)
{
    extern __shared__ char base[];
    const uint32_t sb = smem_u32(base);

    const int t = threadIdx.x, wid = t >> 5, lane = t & 31;
    const int nt = blockIdx.x, b = blockIdx.y;
    const int n0 = nt * 128;
    const int wm = wid & 3;
    const int wn = wid >> 2;

    const int ar = t >> 1, as0 = (t & 1) * 2;
    const __nv_bfloat16* wha = g_wp_hi + (ll)ar * IN_C + as0 * 8;
    const __nv_bfloat16* wla = g_wp_lo + (ll)ar * IN_C + as0 * 8;
    const uint32_t adst = sb + A_HI + ar * A_STR + as0 * 16;

    const int kr = t >> 4, nb = (t & 15) * 8;
    const float* fsrc = feats + ((ll)b * IN_C + kr) * HW + n0 + nb;
    const uint32_t bdst = sb + B_HI + kr * B_STR + nb * 2;

    if (t < 128) ((float*)(base + PREDS))[t] = preds[(ll)b * HW + n0 + t];

    float d[4][4][4];
#pragma unroll
    for (int i = 0; i < 4; i++)
#pragma unroll
        for (int j = 0; j < 4; j++)
#pragma unroll
            for (int k = 0; k < 4; k++) d[i][j][k] = 0.0f;

    float4 bR0, bR1;

    bR0 = *(const float4*)(fsrc);
    bR1 = *(const float4*)(fsrc + 4);
    cpasync16(adst,                      wha);
    cpasync16(adst + 16,                 wha + 8);
    cpasync16(adst + (A_LO - A_HI),      wla);
    cpasync16(adst + (A_LO - A_HI) + 16, wla + 8);
    CP_COMMIT();
    {
        uint2 h0, l0, h1, l1;
        split4(bR0, h0, l0); split4(bR1, h1, l1);
        *(uint4*)(base + (bdst - sb))                 = make_uint4(h0.x, h0.y, h1.x, h1.y);
        *(uint4*)(base + (bdst - sb) + (B_LO - B_HI)) = make_uint4(l0.x, l0.y, l1.x, l1.y);
    }
    CP_WAIT0();
    __syncthreads();

    for (int c = 0; c < NCHUNK; c++) {
        if (c + 1 < NCHUNK) {
            const ll ko = (ll)(c + 1) * KC;
            bR0 = *(const float4*)(fsrc + ko * HW);
            bR1 = *(const float4*)(fsrc + ko * HW + 4);
            const uint32_t db = ((c + 1) & 1) * BUF;
            cpasync16(adst + db,                      wha + ko);
            cpasync16(adst + db + 16,                 wha + ko + 8);
            cpasync16(adst + db + (A_LO - A_HI),      wla + ko);
            cpasync16(adst + db + (A_LO - A_HI) + 16, wla + ko + 8);
            CP_COMMIT();
        }

        const uint32_t bu = sb + (c & 1) * BUF;
#pragma unroll
        for (int s = 0; s < 2; s++) {
            uint32_t bh[4][2], bl[4][2];
            const int krr = s * 16 + (lane & 15);
#pragma unroll
            for (int nf = 0; nf < 4; nf++) {
                uint32_t ba = bu + B_HI + krr * B_STR + (wn * 32 + nf * 8) * 2;
                ldsm_x2t(bh[nf], ba);
                ldsm_x2t(bl[nf], ba + (B_LO - B_HI));
            }
#pragma unroll
            for (int mf = 0; mf < 4; mf++) {
                const int arr = wm * 64 + mf * 16 + (lane & 15);
                const uint32_t acol = (s * 16 + ((lane >> 4) << 3)) * 2;
                uint32_t aa = bu + A_HI + arr * A_STR + acol;
                uint32_t ah[4], al[4];
                ldsm_x4(ah, aa);
                ldsm_x4(al, aa + (A_LO - A_HI));
#pragma unroll
                for (int nf = 0; nf < 4; nf++) mma_bf16(d[mf][nf], ah, bh[nf]);
#pragma unroll
                for (int nf = 0; nf < 4; nf++) mma_bf16(d[mf][nf], ah, bl[nf]);
#pragma unroll
                for (int nf = 0; nf < 4; nf++) mma_bf16(d[mf][nf], al, bh[nf]);
            }
        }
        __syncthreads();

        if (c + 1 < NCHUNK) {
            const uint32_t db = ((c + 1) & 1) * BUF;
            uint2 h0, l0, h1, l1;
            split4(bR0, h0, l0); split4(bR1, h1, l1);
            *(uint4*)(base + (bdst - sb) + db)                 = make_uint4(h0.x, h0.y, h1.x, h1.y);
            *(uint4*)(base + (bdst - sb) + db + (B_LO - B_HI)) = make_uint4(l0.x, l0.y, l1.x, l1.y);
            CP_WAIT0();
        }
        __syncthreads();
    }

    const float* ps = (const float*)(base + PREDS);
    const int r = lane >> 2, cq = lane & 3;
#pragma unroll
    for (int mf = 0; mf < 4; mf++) {
        const int oa = wm * 64 + mf * 16 + r;
        const int oc = oa + 8;
        const float biasa = bias_p[oa], biasb = bias_p[oc];
        float* xa = out + ((ll)b * 2 * CODE + CODE + oa) * HW + n0;
        float* xc = out + ((ll)b * 2 * CODE + CODE + oc) * HW + n0;
        float ra = 0.0f, rb = 0.0f;
#pragma unroll
        for (int nf = 0; nf < 4; nf++) {
            const int nl = wn * 32 + nf * 8 + cq * 2;
            const float p0 = ps[nl], p1 = ps[nl + 1];
            float v0 = d[mf][nf][0] + biasa, v1 = d[mf][nf][1] + biasa;
            float v2 = d[mf][nf][2] + biasb, v3 = d[mf][nf][3] + biasb;
            ra += v0 * p0 + v1 * p1;
            rb += v2 * p0 + v3 * p1;
            *(float2*)(xa + nl) = make_float2(v0, v1);
            *(float2*)(xc + nl) = make_float2(v2, v3);
        }
        ra += __shfl_xor_sync(0xffffffffu, ra, 1);
        ra += __shfl_xor_sync(0xffffffffu, ra, 2);
        rb += __shfl_xor_sync(0xffffffffu, rb, 1);
        rb += __shfl_xor_sync(0xffffffffu, rb, 2);
        if (cq == 0) {
            g_partial[((ll)b * CODE + oa) * NTP + nt * 4 + wn] = ra;
            g_partial[((ll)b * CODE + oc) * NTP + nt * 4 + wn] = rb;
        }
    }
}

// ===========================================================================
// Kernel 2a: parallel feat reduction, coalesced.
// ===========================================================================
__global__ __launch_bounds__(1024) void feat_reduce_kernel() {
    const int gid = blockIdx.x * 1024 + threadIdx.x;
    const int row = gid >> 2, i = gid & 3;
    const float* p = g_partial + (ll)row * NTP + i * 4;
    float s = 0.0f;
#pragma unroll
    for (int q = 0; q < 8; q++) {
        float4 v = *(const float4*)(p + q * 16);
        s += v.x + v.y + v.z + v.w;
    }
    s += __shfl_xor_sync(0xffffffffu, s, 1);
    s += __shfl_xor_sync(0xffffffffu, s, 2);
    if (i == 0) g_feat[row] = s * (1.0f / HW);
}

// ===========================================================================
// Kernel 2b: class-parallel EMA scan (4 blocks, one per class).
// ===========================================================================
#define SMEM_SCAN ((MEMN * CODE + BB * CODE + 96) * 4)

__global__ __launch_bounds__(672) void queue_scan_kernel(
    const float* __restrict__ queue_in, const int* __restrict__ labels_raw,
    const int* __restrict__ flag)
{
    extern __shared__ float sm[];
    float* s_q = sm;
    float* s_feat = sm + MEMN * CODE;
    float* s_logit = s_feat + BB * CODE;
    float* s_fnorm = s_logit + MEMN;
    float* s_coef  = s_fnorm + 1;
    int*   s_lab   = (int*)(s_coef + MEMN);

    const int cls = blockIdx.x;
    const int t = threadIdx.x;
    const float* qsrc = queue_in + (ll)cls * MEMN * CODE;
    for (int i = t; i < MEMN * CODE; i += 672) s_q[i] = qsrc[i];
    for (int i = t; i < BB * CODE; i += 672) s_feat[i] = g_feat[i];
    if (t < BB) s_lab[t] = get_label(labels_raw, t);
    __syncthreads();

    if (*flag == 1) {
        const int warp = t >> 5, lane = t & 31;
        for (int b = 0; b < BB; b++) {
            if (s_lab[b] != cls) continue;
            const float* f = s_feat + b * CODE;

            if (warp < MEMN) {
                const float* slot = s_q + warp * CODE;
                float s = 0.0f;
#pragma unroll
                for (int c = lane; c < CODE; c += 32) s += slot[c] * f[c];
#pragma unroll
                for (int off = 16; off; off >>= 1) s += __shfl_xor_sync(0xffffffffu, s, off);
                if (lane == 0) s_logit[warp] = s;
            } else {
                float s = 0.0f;
#pragma unroll
                for (int c = lane; c < CODE; c += 32) { float v = f[c]; s += v * v; }
#pragma unroll
                for (int off = 16; off; off >>= 1) s += __shfl_xor_sync(0xffffffffu, s, off);
                if (lane == 0) *s_fnorm = sqrtf(s);
            }
            __syncthreads();

            if (t < MEMN) {
                const float lg = s_logit[t];
                const float denom = fmaxf(fabsf(lg) * (*s_fnorm), EPSF);
                s_coef[t] = (1.0f - DECAYF) * lg / denom;
            }
            __syncthreads();

            for (int i = t; i < MEMN * CODE; i += 672) {
                const int m = i >> 8, c = i & 255;
                s_q[i] = DECAYF * s_q[i] + s_coef[m] * f[c];
            }
            __syncthreads();
        }
    }

    float* qdst = g_queue + (ll)cls * MEMN * CODE;
    for (int i = t; i < MEMN * CODE; i += 672) qdst[i] = s_q[i];
}

// ===========================================================================
// Kernel 3: SIMT memory attention, 4 n/thread, 64-thread CTAs.
// Grid (HW/256, B) = 512 blocks (3-4 small CTAs/SM, wave-1 balanced).
// Halves LDS.128 broadcasts per FMA vs the 2n version.
// ===========================================================================
__global__ __launch_bounds__(64) void attn_kernel(
    const int* __restrict__ labels_raw, float* __restrict__ out)
{
    const int b = blockIdx.y, n0 = blockIdx.x * 256, t = threadIdx.x;

    __shared__ float sq[MEMN][CODE];
    const int l = get_label(labels_raw, b);
    const float* qsrc = g_queue + (ll)l * MEMN * CODE;
    for (int i = t * 4; i < MEMN * CODE; i += 256)
        *(float4*)(&sq[0][0] + i) = *(const float4*)(qsrc + i);
    __syncthreads();

    const float* xb = out + ((ll)b * 2 * CODE + CODE) * HW;
    float* ob = out + ((ll)b * 2 * CODE) * HW;
    const int j = n0 + t * 4;

    float4 a[MEMN];
#pragma unroll
    for (int m = 0; m < MEMN; m++) a[m] = make_float4(0.f, 0.f, 0.f, 0.f);

#pragma unroll 1
    for (int cqd = 0; cqd < 64; cqd++) {
        const float* xp = xb + (ll)cqd * 4 * HW + j;
        float4 x0 = *(const float4*)(xp);
        float4 x1 = *(const float4*)(xp + HW);
        float4 x2 = *(const float4*)(xp + 2 * HW);
        float4 x3 = *(const float4*)(xp + 3 * HW);
#pragma unroll
        for (int m = 0; m < MEMN; m++) {
            float4 qv = *(const float4*)&sq[m][cqd * 4];
            a[m].x += qv.x * x0.x + qv.y * x1.x + qv.z * x2.x + qv.w * x3.x;
            a[m].y += qv.x * x0.y + qv.y * x1.y + qv.z * x2.y + qv.w * x3.y;
            a[m].z += qv.x * x0.z + qv.y * x1.z + qv.z * x2.z + qv.w * x3.z;
            a[m].w += qv.x * x0.w + qv.y * x1.w + qv.z * x2.w + qv.w * x3.w;
        }
    }

    // softmax over m, per n lane, in registers
    float4 mx = a[0];
#pragma unroll
    for (int m = 1; m < MEMN; m++) {
        mx.x = fmaxf(mx.x, a[m].x); mx.y = fmaxf(mx.y, a[m].y);
        mx.z = fmaxf(mx.z, a[m].z); mx.w = fmaxf(mx.w, a[m].w);
    }
    float4 s = make_float4(0.f, 0.f, 0.f, 0.f);
#pragma unroll
    for (int m = 0; m < MEMN; m++) {
        a[m].x = __expf(a[m].x - mx.x); s.x += a[m].x;
        a[m].y = __expf(a[m].y - mx.y); s.y += a[m].y;
        a[m].z = __expf(a[m].z - mx.z); s.z += a[m].z;
        a[m].w = __expf(a[m].w - mx.w); s.w += a[m].w;
    }
    const float4 inv = make_float4(1.f / s.x, 1.f / s.y, 1.f / s.z, 1.f / s.w);
#pragma unroll
    for (int m = 0; m < MEMN; m++) {
        a[m].x *= inv.x; a[m].y *= inv.y; a[m].z *= inv.z; a[m].w *= inv.w;
    }

    // new_feat[c][j..j+3] = sum_m q[m][c] * attn[m]
#pragma unroll 1
    for (int cqd = 0; cqd < 64; cqd++) {
        float4 o0 = make_float4(0.f, 0.f, 0.f, 0.f);
        float4 o1 = make_float4(0.f, 0.f, 0.f, 0.f);
        float4 o2 = make_float4(0.f, 0.f, 0.f, 0.f);
        float4 o3 = make_float4(0.f, 0.f, 0.f, 0.f);
#pragma unroll
        for (int m = 0; m < MEMN; m++) {
            float4 qv = *(const float4*)&sq[m][cqd * 4];
            o0.x += qv.x * a[m].x; o0.y += qv.x * a[m].y; o0.z += qv.x * a[m].z; o0.w += qv.x * a[m].w;
            o1.x += qv.y * a[m].x; o1.y += qv.y * a[m].y; o1.z += qv.y * a[m].z; o1.w += qv.y * a[m].w;
            o2.x += qv.z * a[m].x; o2.y += qv.z * a[m].y; o2.z += qv.z * a[m].z; o2.w += qv.z * a[m].w;
            o3.x += qv.w * a[m].x; o3.y += qv.w * a[m].y; o3.z += qv.w * a[m].z; o3.w += qv.w * a[m].w;
        }
        float* op = ob + (ll)cqd * 4 * HW + j;
        *(float4*)(op)          = o0;
        *(float4*)(op + HW)     = o1;
        *(float4*)(op + 2 * HW) = o2;
        *(float4*)(op + 3 * HW) = o3;
    }
}

// ---------------------------------------------------------------------------
extern "C" void kernel_launch(void* const* d_in, const int* in_sizes, int n_in,
                              void* d_out, int out_size) {
    const float* feats  = (const float*)d_in[0];
    const float* preds  = (const float*)d_in[1];
    const int*   labels = (const int*)  d_in[2];
    const int*   flag   = (const int*)  d_in[3];
    const float* queue  = (const float*)d_in[4];
    const float* Wp     = (const float*)d_in[5];
    const float* bp     = (const float*)d_in[6];
    float* out = (float*)d_out;

    cudaFuncSetAttribute(gemm_proj_mma,
                         cudaFuncAttributeMaxDynamicSharedMemorySize, SMEM_GEMM);
    cudaFuncSetAttribute(queue_scan_kernel,
                         cudaFuncAttributeMaxDynamicSharedMemorySize, SMEM_SCAN);

    convert_wp<<<CODE * IN_C / 1024, 256>>>(Wp);

    dim3 g1(HW / 128, BB);
    gemm_proj_mma<<<g1, 512, SMEM_GEMM>>>(feats, preds, bp, out);

    feat_reduce_kernel<<<BB, 1024>>>();
    queue_scan_kernel<<<NCLASSES, 672, SMEM_SCAN>>>(queue, labels, flag);

    dim3 g3(HW / 256, BB);
    attn_kernel<<<g3, 64>>>(labels, out);
}

// round 16
// speedup vs baseline: 1.0491x; 1.0491x over previous
#include <cuda_runtime.h>
#include <cuda_bf16.h>
#include <cstdint>

#define BB 32
#define IN_C 512
#define HW 4096
#define CODE 256
#define NCLASSES 4
#define MEMN 20
#define DECAYF 0.9f
#define EPSF 1e-12f
#define NTP 128

typedef long long ll;

// Deterministic scratch (no atomics anywhere).
__device__ float g_partial[BB * CODE * NTP];
__device__ float g_feat[BB * CODE];
__device__ float g_queue[NCLASSES * MEMN * CODE];

// Pre-converted bf16 hi/lo of Wp.
__device__ __nv_bfloat16 g_wp_hi[CODE * IN_C];
__device__ __nv_bfloat16 g_wp_lo[CODE * IN_C];

// ---------------------------------------------------------------------------
// helpers
// ---------------------------------------------------------------------------
__device__ __forceinline__ uint32_t smem_u32(const void* p) {
    uint32_t a;
    asm("{ .reg .u64 t; cvta.to.shared.u64 t, %1; cvt.u32.u64 %0, t; }" : "=r"(a) : "l"(p));
    return a;
}
__device__ __forceinline__ void ldsm_x4(uint32_t a[4], uint32_t addr) {
    asm volatile("ldmatrix.sync.aligned.m8n8.x4.shared.b16 {%0,%1,%2,%3}, [%4];"
                 : "=r"(a[0]), "=r"(a[1]), "=r"(a[2]), "=r"(a[3]) : "r"(addr));
}
__device__ __forceinline__ void ldsm_x2t(uint32_t b[2], uint32_t addr) {
    asm volatile("ldmatrix.sync.aligned.m8n8.x2.trans.shared.b16 {%0,%1}, [%2];"
                 : "=r"(b[0]), "=r"(b[1]) : "r"(addr));
}
__device__ __forceinline__ void mma_bf16(float d[4], const uint32_t a[4], const uint32_t b[2]) {
    asm volatile("mma.sync.aligned.m16n8k16.row.col.f32.bf16.bf16.f32 "
                 "{%0,%1,%2,%3}, {%4,%5,%6,%7}, {%8,%9}, {%0,%1,%2,%3};"
                 : "+f"(d[0]), "+f"(d[1]), "+f"(d[2]), "+f"(d[3])
                 : "r"(a[0]), "r"(a[1]), "r"(a[2]), "r"(a[3]), "r"(b[0]), "r"(b[1]));
}
__device__ __forceinline__ void cpasync16(uint32_t dst, const void* src) {
    asm volatile("cp.async.cg.shared.global [%0], [%1], 16;" :: "r"(dst), "l"(src));
}
#define CP_COMMIT() asm volatile("cp.async.commit_group;" ::: "memory")
#define CP_WAIT0()  asm volatile("cp.async.wait_group 0;" ::: "memory")

__device__ __forceinline__ void split4(float4 v, uint2& hi, uint2& lo) {
    __nv_bfloat16 h0 = __float2bfloat16_rn(v.x), h1 = __float2bfloat16_rn(v.y);
    __nv_bfloat16 h2 = __float2bfloat16_rn(v.z), h3 = __float2bfloat16_rn(v.w);
    float r0 = v.x - __bfloat162float(h0), r1 = v.y - __bfloat162float(h1);
    float r2 = v.z - __bfloat162float(h2), r3 = v.w - __bfloat162float(h3);
    __nv_bfloat16 l0 = __float2bfloat16_rn(r0), l1 = __float2bfloat16_rn(r1);
    __nv_bfloat16 l2 = __float2bfloat16_rn(r2), l3 = __float2bfloat16_rn(r3);
    hi.x = (uint32_t)__bfloat16_as_ushort(h0) | ((uint32_t)__bfloat16_as_ushort(h1) << 16);
    hi.y = (uint32_t)__bfloat16_as_ushort(h2) | ((uint32_t)__bfloat16_as_ushort(h3) << 16);
    lo.x = (uint32_t)__bfloat16_as_ushort(l0) | ((uint32_t)__bfloat16_as_ushort(l1) << 16);
    lo.y = (uint32_t)__bfloat16_as_ushort(l2) | ((uint32_t)__bfloat16_as_ushort(l3) << 16);
}

__device__ __forceinline__ int get_label(const int* lab, int i) {
    bool odd_zero = true;
#pragma unroll
    for (int k = 1; k < 32; k += 2) odd_zero &= (lab[k] == 0);
    return odd_zero ? lab[2 * i] : lab[i];
}

// ===========================================================================
// Kernel 0: Wp fp32 -> bf16 hi/lo.
// ===========================================================================
__global__ __launch_bounds__(256) void convert_wp(const float* __restrict__ Wp) {
    const int i = (blockIdx.x * 256 + threadIdx.x) * 4;
    float4 v = *(const float4*)(Wp + i);
    uint2 hi, lo; split4(v, hi, lo);
    *(uint2*)(g_wp_hi + i) = hi;
    *(uint2*)(g_wp_lo + i) = lo;
}

// ===========================================================================
// Kernel 1: HMMA bf16-split GEMM, fused B conversion, M=256 CTA tile.
// (R12 verbatim — two barriers per chunk; measured-correct, protected)
// ===========================================================================
#define KC 32
#define NCHUNK 16
#define A_STR 80
#define B_STR 272
#define A_HI 0
#define A_LO 20480
#define B_HI 40960
#define B_LO 49664
#define BUF 58368
#define PREDS (2 * BUF)
#define SMEM_GEMM (PREDS + 512 + 16)

__global__ __launch_bounds__(512, 1) void gemm_proj_mma(
    const float* __restrict__ feats, const float* __restrict__ preds,
    const float* __restrict__ bias_p, float* __restrict__ out)
{
    extern __shared__ char base[];
    const uint32_t sb = smem_u32(base);

    const int t = threadIdx.x, wid = t >> 5, lane = t & 31;
    const int nt = blockIdx.x, b = blockIdx.y;
    const int n0 = nt * 128;
    const int wm = wid & 3;
    const int wn = wid >> 2;

    const int ar = t >> 1, as0 = (t & 1) * 2;
    const __nv_bfloat16* wha = g_wp_hi + (ll)ar * IN_C + as0 * 8;
    const __nv_bfloat16* wla = g_wp_lo + (ll)ar * IN_C + as0 * 8;
    const uint32_t adst = sb + A_HI + ar * A_STR + as0 * 16;

    const int kr = t >> 4, nb = (t & 15) * 8;
    const float* fsrc = feats + ((ll)b * IN_C + kr) * HW + n0 + nb;
    const uint32_t bdst = sb + B_HI + kr * B_STR + nb * 2;

    if (t < 128) ((float*)(base + PREDS))[t] = preds[(ll)b * HW + n0 + t];

    float d[4][4][4];
#pragma unroll
    for (int i = 0; i < 4; i++)
#pragma unroll
        for (int j = 0; j < 4; j++)
#pragma unroll
            for (int k = 0; k < 4; k++) d[i][j][k] = 0.0f;

    float4 bR0, bR1;

    bR0 = *(const float4*)(fsrc);
    bR1 = *(const float4*)(fsrc + 4);
    cpasync16(adst,                      wha);
    cpasync16(adst + 16,                 wha + 8);
    cpasync16(adst + (A_LO - A_HI),      wla);
    cpasync16(adst + (A_LO - A_HI) + 16, wla + 8);
    CP_COMMIT();
    {
        uint2 h0, l0, h1, l1;
        split4(bR0, h0, l0); split4(bR1, h1, l1);
        *(uint4*)(base + (bdst - sb))                 = make_uint4(h0.x, h0.y, h1.x, h1.y);
        *(uint4*)(base + (bdst - sb) + (B_LO - B_HI)) = make_uint4(l0.x, l0.y, l1.x, l1.y);
    }
    CP_WAIT0();
    __syncthreads();

    for (int c = 0; c < NCHUNK; c++) {
        if (c + 1 < NCHUNK) {
            const ll ko = (ll)(c + 1) * KC;
            bR0 = *(const float4*)(fsrc + ko * HW);
            bR1 = *(const float4*)(fsrc + ko * HW + 4);
            const uint32_t db = ((c + 1) & 1) * BUF;
            cpasync16(adst + db,                      wha + ko);
            cpasync16(adst + db + 16,                 wha + ko + 8);
            cpasync16(adst + db + (A_LO - A_HI),      wla + ko);
            cpasync16(adst + db + (A_LO - A_HI) + 16, wla + ko + 8);
            CP_COMMIT();
        }

        const uint32_t bu = sb + (c & 1) * BUF;
#pragma unroll
        for (int s = 0; s < 2; s++) {
            uint32_t bh[4][2], bl[4][2];
            const int krr = s * 16 + (lane & 15);
#pragma unroll
            for (int nf = 0; nf < 4; nf++) {
                uint32_t ba = bu + B_HI + krr * B_STR + (wn * 32 + nf * 8) * 2;
                ldsm_x2t(bh[nf], ba);
                ldsm_x2t(bl[nf], ba + (B_LO - B_HI));
            }
#pragma unroll
            for (int mf = 0; mf < 4; mf++) {
                const int arr = wm * 64 + mf * 16 + (lane & 15);
                const uint32_t acol = (s * 16 + ((lane >> 4) << 3)) * 2;
                uint32_t aa = bu + A_HI + arr * A_STR + acol;
                uint32_t ah[4], al[4];
                ldsm_x4(ah, aa);
                ldsm_x4(al, aa + (A_LO - A_HI));
#pragma unroll
                for (int nf = 0; nf < 4; nf++) mma_bf16(d[mf][nf], ah, bh[nf]);
#pragma unroll
                for (int nf = 0; nf < 4; nf++) mma_bf16(d[mf][nf], ah, bl[nf]);
#pragma unroll
                for (int nf = 0; nf < 4; nf++) mma_bf16(d[mf][nf], al, bh[nf]);
            }
        }
        __syncthreads();

        if (c + 1 < NCHUNK) {
            const uint32_t db = ((c + 1) & 1) * BUF;
            uint2 h0, l0, h1, l1;
            split4(bR0, h0, l0); split4(bR1, h1, l1);
            *(uint4*)(base + (bdst - sb) + db)                 = make_uint4(h0.x, h0.y, h1.x, h1.y);
            *(uint4*)(base + (bdst - sb) + db + (B_LO - B_HI)) = make_uint4(l0.x, l0.y, l1.x, l1.y);
            CP_WAIT0();
        }
        __syncthreads();
    }

    const float* ps = (const float*)(base + PREDS);
    const int r = lane >> 2, cq = lane & 3;
#pragma unroll
    for (int mf = 0; mf < 4; mf++) {
        const int oa = wm * 64 + mf * 16 + r;
        const int oc = oa + 8;
        const float biasa = bias_p[oa], biasb = bias_p[oc];
        float* xa = out + ((ll)b * 2 * CODE + CODE + oa) * HW + n0;
        float* xc = out + ((ll)b * 2 * CODE + CODE + oc) * HW + n0;
        float ra = 0.0f, rb = 0.0f;
#pragma unroll
        for (int nf = 0; nf < 4; nf++) {
            const int nl = wn * 32 + nf * 8 + cq * 2;
            const float p0 = ps[nl], p1 = ps[nl + 1];
            float v0 = d[mf][nf][0] + biasa, v1 = d[mf][nf][1] + biasa;
            float v2 = d[mf][nf][2] + biasb, v3 = d[mf][nf][3] + biasb;
            ra += v0 * p0 + v1 * p1;
            rb += v2 * p0 + v3 * p1;
            *(float2*)(xa + nl) = make_float2(v0, v1);
            *(float2*)(xc + nl) = make_float2(v2, v3);
        }
        ra += __shfl_xor_sync(0xffffffffu, ra, 1);
        ra += __shfl_xor_sync(0xffffffffu, ra, 2);
        rb += __shfl_xor_sync(0xffffffffu, rb, 1);
        rb += __shfl_xor_sync(0xffffffffu, rb, 2);
        if (cq == 0) {
            g_partial[((ll)b * CODE + oa) * NTP + nt * 4 + wn] = ra;
            g_partial[((ll)b * CODE + oc) * NTP + nt * 4 + wn] = rb;
        }
    }
}

// ===========================================================================
// Kernel 2a: parallel feat reduction, coalesced.
// ===========================================================================
__global__ __launch_bounds__(1024) void feat_reduce_kernel() {
    const int gid = blockIdx.x * 1024 + threadIdx.x;
    const int row = gid >> 2, i = gid & 3;
    const float* p = g_partial + (ll)row * NTP + i * 4;
    float s = 0.0f;
#pragma unroll
    for (int q = 0; q < 8; q++) {
        float4 v = *(const float4*)(p + q * 16);
        s += v.x + v.y + v.z + v.w;
    }
    s += __shfl_xor_sync(0xffffffffu, s, 1);
    s += __shfl_xor_sync(0xffffffffu, s, 2);
    if (i == 0) g_feat[row] = s * (1.0f / HW);
}

// ===========================================================================
// Kernel 2b: class-parallel EMA scan (4 blocks, one per class).
// ===========================================================================
#define SMEM_SCAN ((MEMN * CODE + BB * CODE + 96) * 4)

__global__ __launch_bounds__(672) void queue_scan_kernel(
    const float* __restrict__ queue_in, const int* __restrict__ labels_raw,
    const int* __restrict__ flag)
{
    extern __shared__ float sm[];
    float* s_q = sm;
    float* s_feat = sm + MEMN * CODE;
    float* s_logit = s_feat + BB * CODE;
    float* s_fnorm = s_logit + MEMN;
    float* s_coef  = s_fnorm + 1;
    int*   s_lab   = (int*)(s_coef + MEMN);

    const int cls = blockIdx.x;
    const int t = threadIdx.x;
    const float* qsrc = queue_in + (ll)cls * MEMN * CODE;
    for (int i = t; i < MEMN * CODE; i += 672) s_q[i] = qsrc[i];
    for (int i = t; i < BB * CODE; i += 672) s_feat[i] = g_feat[i];
    if (t < BB) s_lab[t] = get_label(labels_raw, t);
    __syncthreads();

    if (*flag == 1) {
        const int warp = t >> 5, lane = t & 31;
        for (int b = 0; b < BB; b++) {
            if (s_lab[b] != cls) continue;
            const float* f = s_feat + b * CODE;

            if (warp < MEMN) {
                const float* slot = s_q + warp * CODE;
                float s = 0.0f;
#pragma unroll
                for (int c = lane; c < CODE; c += 32) s += slot[c] * f[c];
#pragma unroll
                for (int off = 16; off; off >>= 1) s += __shfl_xor_sync(0xffffffffu, s, off);
                if (lane == 0) s_logit[warp] = s;
            } else {
                float s = 0.0f;
#pragma unroll
                for (int c = lane; c < CODE; c += 32) { float v = f[c]; s += v * v; }
#pragma unroll
                for (int off = 16; off; off >>= 1) s += __shfl_xor_sync(0xffffffffu, s, off);
                if (lane == 0) *s_fnorm = sqrtf(s);
            }
            __syncthreads();

            if (t < MEMN) {
                const float lg = s_logit[t];
                const float denom = fmaxf(fabsf(lg) * (*s_fnorm), EPSF);
                s_coef[t] = (1.0f - DECAYF) * lg / denom;
            }
            __syncthreads();

            for (int i = t; i < MEMN * CODE; i += 672) {
                const int m = i >> 8, c = i & 255;
                s_q[i] = DECAYF * s_q[i] + s_coef[m] * f[c];
            }
            __syncthreads();
        }
    }

    float* qdst = g_queue + (ll)cls * MEMN * CODE;
    for (int i = t; i < MEMN * CODE; i += 672) qdst[i] = s_q[i];
}

// ===========================================================================
// Kernel 3: SIMT memory attention (R12 shape: 128 threads, 512 blocks,
// 2 n/thread) with the logit c-loop unrolled x2 -> 8 LDGs in flight.
// ===========================================================================
__global__ __launch_bounds__(128) void attn_kernel(
    const int* __restrict__ labels_raw, float* __restrict__ out)
{
    const int b = blockIdx.y, n0 = blockIdx.x * 256, t = threadIdx.x;

    __shared__ float sq[MEMN][CODE];
    const int l = get_label(labels_raw, b);
    const float* qsrc = g_queue + (ll)l * MEMN * CODE;
    for (int i = t * 4; i < MEMN * CODE; i += 512)
        *(float4*)(&sq[0][0] + i) = *(const float4*)(qsrc + i);
    __syncthreads();

    const float* xb = out + ((ll)b * 2 * CODE + CODE) * HW;
    float* ob = out + ((ll)b * 2 * CODE) * HW;
    const int j = n0 + t * 2;

    float a0[MEMN], a1[MEMN];
#pragma unroll
    for (int m = 0; m < MEMN; m++) { a0[m] = 0.f; a1[m] = 0.f; }

    // logit phase, unrolled x2: 8 LDGs in flight before the FMA block
#pragma unroll 1
    for (int cqd = 0; cqd < 64; cqd += 2) {
        const float* xp = xb + (ll)cqd * 4 * HW + j;
        float2 x0 = *(const float2*)(xp);
        float2 x1 = *(const float2*)(xp + HW);
        float2 x2 = *(const float2*)(xp + 2 * HW);
        float2 x3 = *(const float2*)(xp + 3 * HW);
        float2 x4 = *(const float2*)(xp + 4 * HW);
        float2 x5 = *(const float2*)(xp + 5 * HW);
        float2 x6 = *(const float2*)(xp + 6 * HW);
        float2 x7 = *(const float2*)(xp + 7 * HW);
#pragma unroll
        for (int m = 0; m < MEMN; m++) {
            float4 qv = *(const float4*)&sq[m][cqd * 4];
            float4 qw = *(const float4*)&sq[m][cqd * 4 + 4];
            a0[m] += qv.x * x0.x + qv.y * x1.x + qv.z * x2.x + qv.w * x3.x
                   + qw.x * x4.x + qw.y * x5.x + qw.z * x6.x + qw.w * x7.x;
            a1[m] += qv.x * x0.y + qv.y * x1.y + qv.z * x2.y + qv.w * x3.y
                   + qw.x * x4.y + qw.y * x5.y + qw.z * x6.y + qw.w * x7.y;
        }
    }

    float m0 = a0[0], m1 = a1[0];
#pragma unroll
    for (int m = 1; m < MEMN; m++) { m0 = fmaxf(m0, a0[m]); m1 = fmaxf(m1, a1[m]); }
    float s0 = 0.f, s1 = 0.f;
#pragma unroll
    for (int m = 0; m < MEMN; m++) {
        a0[m] = __expf(a0[m] - m0); s0 += a0[m];
        a1[m] = __expf(a1[m] - m1); s1 += a1[m];
    }
    const float i0 = 1.f / s0, i1 = 1.f / s1;
#pragma unroll
    for (int m = 0; m < MEMN; m++) { a0[m] *= i0; a1[m] *= i1; }

#pragma unroll 1
    for (int cqd = 0; cqd < 64; cqd++) {
        float o0x = 0.f, o0y = 0.f, o1x = 0.f, o1y = 0.f;
        float o2x = 0.f, o2y = 0.f, o3x = 0.f, o3y = 0.f;
#pragma unroll
        for (int m = 0; m < MEMN; m++) {
            float4 qv = *(const float4*)&sq[m][cqd * 4];
            o0x += qv.x * a0[m]; o0y += qv.x * a1[m];
            o1x += qv.y * a0[m]; o1y += qv.y * a1[m];
            o2x += qv.z * a0[m]; o2y += qv.z * a1[m];
            o3x += qv.w * a0[m]; o3y += qv.w * a1[m];
        }
        float* op = ob + (ll)cqd * 4 * HW + j;
        *(float2*)(op)          = make_float2(o0x, o0y);
        *(float2*)(op + HW)     = make_float2(o1x, o1y);
        *(float2*)(op + 2 * HW) = make_float2(o2x, o2y);
        *(float2*)(op + 3 * HW) = make_float2(o3x, o3y);
    }
}

// ---------------------------------------------------------------------------
extern "C" void kernel_launch(void* const* d_in, const int* in_sizes, int n_in,
                              void* d_out, int out_size) {
    const float* feats  = (const float*)d_in[0];
    const float* preds  = (const float*)d_in[1];
    const int*   labels = (const int*)  d_in[2];
    const int*   flag   = (const int*)  d_in[3];
    const float* queue  = (const float*)d_in[4];
    const float* Wp     = (const float*)d_in[5];
    const float* bp     = (const float*)d_in[6];
    float* out = (float*)d_out;

    cudaFuncSetAttribute(gemm_proj_mma,
                         cudaFuncAttributeMaxDynamicSharedMemorySize, SMEM_GEMM);
    cudaFuncSetAttribute(queue_scan_kernel,
                         cudaFuncAttributeMaxDynamicSharedMemorySize, SMEM_SCAN);

    convert_wp<<<CODE * IN_C / 1024, 256>>>(Wp);

    dim3 g1(HW / 128, BB);
    gemm_proj_mma<<<g1, 512, SMEM_GEMM>>>(feats, preds, bp, out);

    feat_reduce_kernel<<<BB, 1024>>>();
    queue_scan_kernel<<<NCLASSES, 672, SMEM_SCAN>>>(queue, labels, flag);

    dim3 g3(HW / 256, BB);
    attn_kernel<<<g3, 128>>>(labels, out);
}